// round 2
// baseline (speedup 1.0000x reference)
#include <cuda_runtime.h>
#include <cstdint>

// ScaledDotProductAttention: B=4,H=16,S=2048,D=64 fp32, mask [B,1,S,S] int32.
// Outputs: out [B,H,S,D] followed by weights [B,H,S,S] concatenated in d_out.
//
// Strategy (round 0 baseline, f32x2 packed-FMA, no-max softmax):
//   grid = (S/64 q-tiles, B*H). Each CTA owns 64 query rows of one head.
//   Pass 1: per 64-wide K tile: scores via f32x2 FMAs, e = mask?exp(s/8):0,
//           write e to gmem weights (scratch-in-place), accumulate rowsum and
//           unnormalized o += e*V.
//   Epilogue: rowsum reduce -> rinv; write out = o*rinv; rescale the CTA's
//           weight rows in place (L2-hot).

#define B_ 4
#define H_ 16
#define S_ 2048
#define D_ 64

constexpr int BQ  = 64;
constexpr int BK  = 64;
constexpr int NT  = 256;   // threads
constexpr int STR = 68;    // smem row stride in floats (16B-aligned, bank-friendly)

// smem layout (floats)
constexpr int QS   = 0;
constexpr int KT   = QS + 64 * STR;   // K transposed: row = d, col = k
constexpr int VS   = KT + 64 * STR;   // V row-major: row = k, col = d
constexpr int ES   = VS + 64 * STR;   // e tile row-major: row = q, col = k
constexpr int RED  = ES + 64 * STR;   // [16][STR] rowsum partials
constexpr int RINV = RED + 16 * STR;
constexpr int SMEM_FLOATS = RINV + 64;
constexpr int SMEM_BYTES  = SMEM_FLOATS * 4;

typedef unsigned long long ull;

__device__ __forceinline__ ull dup2(float x) {
    ull r; asm("mov.b64 %0, {%1, %1};" : "=l"(r) : "f"(x)); return r;
}
__device__ __forceinline__ void fma2(ull& d, ull a, ull b) {
    asm("fma.rn.f32x2 %0, %1, %2, %0;" : "+l"(d) : "l"(a), "l"(b));
}
__device__ __forceinline__ void unpack2(ull v, float& lo, float& hi) {
    asm("mov.b64 {%0, %1}, %2;" : "=f"(lo), "=f"(hi) : "l"(v));
}

__global__ void __launch_bounds__(NT, 2)
sdpa_kernel(const float* __restrict__ Q, const float* __restrict__ K,
            const float* __restrict__ V, const int* __restrict__ mask,
            float* __restrict__ out, float* __restrict__ wts)
{
    extern __shared__ float sm[];

    const int tid = threadIdx.x;
    const int tc  = tid & 15;   // 16 col-groups (4 cols each)
    const int tr  = tid >> 4;   // 16 row-groups (4 rows each)
    const int bh  = blockIdx.y;
    const int b   = bh >> 4;    // H = 16
    const int q0  = blockIdx.x * BQ;

    const float* Qg = Q + ((size_t)bh * S_ + q0) * D_;
    const float* Kg = K + (size_t)bh * S_ * D_;
    const float* Vg = V + (size_t)bh * S_ * D_;
    const int*   Mg = mask + ((size_t)b * S_ + q0) * S_;
    float*       Wg = wts  + ((size_t)bh * S_ + q0) * S_;
    float*       Og = out  + ((size_t)bh * S_ + q0) * D_;

    // ---- load Q tile (row-major, coalesced float4) ----
    for (int idx = tid; idx < BQ * (D_ / 4); idx += NT) {
        int r = idx >> 4, c4 = idx & 15;
        float4 v = *(const float4*)(Qg + (size_t)r * D_ + 4 * c4);
        *(float4*)&sm[QS + r * STR + 4 * c4] = v;
    }

    ull   o2[4][2];
    float rs[4];
    #pragma unroll
    for (int i = 0; i < 4; ++i) { o2[i][0] = 0ull; o2[i][1] = 0ull; rs[i] = 0.f; }

    const float sc = 0.125f;  // 1/sqrt(64)

    for (int kt = 0; kt < S_ / BK; ++kt) {
        const int k0 = kt * BK;
        __syncthreads();   // prev PV done before overwriting KT/VS

        // ---- load K tile transposed (conflict-free smem writes) ----
        {
            int k = tid & 63;
            int g = tid >> 6;  // 0..3
            #pragma unroll
            for (int it = 0; it < 4; ++it) {
                int d4 = g * 4 + it;  // 0..15
                float4 v = *(const float4*)(Kg + (size_t)(k0 + k) * D_ + 4 * d4);
                sm[KT + (4 * d4 + 0) * STR + k] = v.x;
                sm[KT + (4 * d4 + 1) * STR + k] = v.y;
                sm[KT + (4 * d4 + 2) * STR + k] = v.z;
                sm[KT + (4 * d4 + 3) * STR + k] = v.w;
            }
        }
        // ---- load V tile row-major ----
        for (int idx = tid; idx < BK * (D_ / 4); idx += NT) {
            int r = idx >> 4, c4 = idx & 15;
            *(float4*)&sm[VS + r * STR + 4 * c4] =
                *(const float4*)(Vg + (size_t)(k0 + r) * D_ + 4 * c4);
        }
        // ---- prefetch mask (regs) ----
        int4 mreg[4];
        #pragma unroll
        for (int i = 0; i < 4; ++i)
            mreg[i] = *(const int4*)(Mg + (size_t)(4 * tr + i) * S_ + k0 + 4 * tc);

        __syncthreads();

        // ---- scores: s2[i][jp] packs k-cols (4tc+2jp, 4tc+2jp+1), full sum over d ----
        ull s2[4][2];
        #pragma unroll
        for (int i = 0; i < 4; ++i) { s2[i][0] = 0ull; s2[i][1] = 0ull; }

        #pragma unroll 4
        for (int dd = 0; dd < D_; dd += 2) {
            ulonglong2 kA = *(const ulonglong2*)&sm[KT + (dd    ) * STR + 4 * tc];
            ulonglong2 kB = *(const ulonglong2*)&sm[KT + (dd + 1) * STR + 4 * tc];
            #pragma unroll
            for (int i = 0; i < 4; ++i) {
                float2 q01 = *(const float2*)&sm[QS + (4 * tr + i) * STR + dd];
                ull qe = dup2(q01.x), qo = dup2(q01.y);
                fma2(s2[i][0], qe, kA.x);
                fma2(s2[i][1], qe, kA.y);
                fma2(s2[i][0], qo, kB.x);
                fma2(s2[i][1], qo, kB.y);
            }
        }

        // ---- e = mask ? exp(s*sc) : 0 ; write smem + gmem ; rowsum ----
        #pragma unroll
        for (int i = 0; i < 4; ++i) {
            float s0, s1, s2v, s3;
            unpack2(s2[i][0], s0, s1);
            unpack2(s2[i][1], s2v, s3);
            float e0 = mreg[i].x ? __expf(s0  * sc) : 0.f;
            float e1 = mreg[i].y ? __expf(s1  * sc) : 0.f;
            float e2 = mreg[i].z ? __expf(s2v * sc) : 0.f;
            float e3 = mreg[i].w ? __expf(s3  * sc) : 0.f;
            float4 ev = make_float4(e0, e1, e2, e3);
            *(float4*)&sm[ES + (4 * tr + i) * STR + 4 * tc] = ev;
            *(float4*)(Wg + (size_t)(4 * tr + i) * S_ + k0 + 4 * tc) = ev;
            rs[i] += (e0 + e1) + (e2 + e3);
        }
        __syncthreads();

        // ---- PV: o2[i][jp] packs d-cols (4tc+2jp, 4tc+2jp+1) ----
        #pragma unroll 4
        for (int k = 0; k < BK; k += 2) {
            ulonglong2 vA = *(const ulonglong2*)&sm[VS + (k    ) * STR + 4 * tc];
            ulonglong2 vB = *(const ulonglong2*)&sm[VS + (k + 1) * STR + 4 * tc];
            #pragma unroll
            for (int i = 0; i < 4; ++i) {
                float2 e01 = *(const float2*)&sm[ES + (4 * tr + i) * STR + k];
                ull ea = dup2(e01.x), eb = dup2(e01.y);
                fma2(o2[i][0], ea, vA.x);
                fma2(o2[i][1], ea, vA.y);
                fma2(o2[i][0], eb, vB.x);
                fma2(o2[i][1], eb, vB.y);
            }
        }
    }

    // ---- rowsum reduce -> rinv ----
    #pragma unroll
    for (int i = 0; i < 4; ++i)
        sm[RED + tc * STR + 4 * tr + i] = rs[i];
    __syncthreads();
    if (tid < 64) {
        float s = 0.f;
        #pragma unroll
        for (int t = 0; t < 16; ++t) s += sm[RED + t * STR + tid];
        sm[RINV + tid] = 1.0f / s;
    }
    __syncthreads();

    // ---- write out = o * rinv ----
    #pragma unroll
    for (int i = 0; i < 4; ++i) {
        float ri = sm[RINV + 4 * tr + i];
        float a0, a1, a2, a3;
        unpack2(o2[i][0], a0, a1);
        unpack2(o2[i][1], a2, a3);
        float4 ov = make_float4(a0 * ri, a1 * ri, a2 * ri, a3 * ri);
        *(float4*)(Og + (size_t)(4 * tr + i) * D_ + 4 * tc) = ov;
    }

    // ---- pass 2: rescale this CTA's weight rows in place (L2-hot) ----
    for (int idx = tid; idx < BQ * (S_ / 4); idx += NT) {
        int r  = idx >> 9;        // S_/4 = 512 float4 per row
        int c4 = idx & 511;
        float ri = sm[RINV + r];
        float4* p = (float4*)(Wg + (size_t)r * S_) + c4;
        float4 v = *p;
        v.x *= ri; v.y *= ri; v.z *= ri; v.w *= ri;
        *p = v;
    }
}

extern "C" void kernel_launch(void* const* d_in, const int* in_sizes, int n_in,
                              void* d_out, int out_size)
{
    const float* Q    = (const float*)d_in[0];
    const float* K    = (const float*)d_in[1];
    const float* V    = (const float*)d_in[2];
    const int*   mask = (const int*)d_in[3];

    float* out = (float*)d_out;
    float* wts = out + (size_t)B_ * H_ * S_ * D_;   // weights follow out

    cudaFuncSetAttribute(sdpa_kernel,
                         cudaFuncAttributeMaxDynamicSharedMemorySize, SMEM_BYTES);

    dim3 grid(S_ / BQ, B_ * H_);
    sdpa_kernel<<<grid, NT, SMEM_BYTES>>>(Q, K, V, mask, out, wts);
}

// round 4
// speedup vs baseline: 1.3630x; 1.3630x over previous
#include <cuda_runtime.h>
#include <cuda_bf16.h>
#include <cstdint>

// ScaledDotProductAttention B=4,H=16,S=2048,D=64 fp32 + mask [B,1,S,S] int32.
// out [B,H,S,D] then weights [B,H,S,S] concatenated in d_out.
//
// mma.sync (HMMA, bf16 2-way split) flash-style, two-pass normalization:
//   pass A: QK^T + masked exp -> row sums -> g_rsum scratch.
//   pass B: recompute identical scores, W = e*rinv streamed out (f32),
//           P kept in registers as PV A-fragments, O accumulated in regs.

#define B_ 4
#define H_ 16
#define S_ 2048
#define D_ 64

constexpr int BM = 128, BN = 128, NT = 256, NTILE = S_ / BN;
constexpr int KSTR = 72;          // bf16 elems per smem row (pad)
constexpr int RB   = KSTR * 2;    // 144 bytes per row

constexpr int OFF_QH = 0;
constexpr int OFF_QL = OFF_QH + BM * RB;   // 18432
constexpr int OFF_KH = OFF_QL + BM * RB;   // 36864
constexpr int OFF_KL = OFF_KH + BM * RB;   // 55296
constexpr int OFF_VH = OFF_KL + BM * RB;   // 73728
constexpr int OFF_VL = OFF_VH + BM * RB;   // 92160
constexpr int OFF_REDA = OFF_VH;           // pass A: 256-float reduce area
constexpr int SMEM_A = OFF_VH + 1024;      // 74752
constexpr int OFF_RINV = OFF_VL + BM * RB; // 110592
constexpr int SMEM_B = OFF_RINV + 512;     // 111104

__device__ float g_rsum[B_ * H_ * S_];     // 512KB scratch (rowsums)

// ---------- helpers ----------
__device__ __forceinline__ uint32_t smem_u32(const void* p) {
    uint32_t a;
    asm("{ .reg .u64 t; cvta.to.shared.u64 t, %1; cvt.u32.u64 %0, t; }" : "=r"(a) : "l"(p));
    return a;
}

__device__ __forceinline__ void ldsm4(uint32_t* r, uint32_t a) {
    asm volatile("ldmatrix.sync.aligned.m8n8.x4.shared.b16 {%0,%1,%2,%3}, [%4];"
                 : "=r"(r[0]), "=r"(r[1]), "=r"(r[2]), "=r"(r[3]) : "r"(a));
}
__device__ __forceinline__ void ldsm4t(uint32_t* r, uint32_t a) {
    asm volatile("ldmatrix.sync.aligned.m8n8.x4.trans.shared.b16 {%0,%1,%2,%3}, [%4];"
                 : "=r"(r[0]), "=r"(r[1]), "=r"(r[2]), "=r"(r[3]) : "r"(a));
}
__device__ __forceinline__ void mma_bf16(float* c, const uint32_t* a, uint32_t b0, uint32_t b1) {
    asm volatile(
        "mma.sync.aligned.m16n8k16.row.col.f32.bf16.bf16.f32 "
        "{%0,%1,%2,%3}, {%4,%5,%6,%7}, {%8,%9}, {%0,%1,%2,%3};"
        : "+f"(c[0]), "+f"(c[1]), "+f"(c[2]), "+f"(c[3])
        : "r"(a[0]), "r"(a[1]), "r"(a[2]), "r"(a[3]), "r"(b0), "r"(b1));
}

// split (a,b) into packed bf16x2 hi + lo
__device__ __forceinline__ void split2pack(float a, float b, uint32_t& hp, uint32_t& lp) {
    __nv_bfloat162 h = __floats2bfloat162_rn(a, b);
    float2 hf = __bfloat1622float2(h);
    __nv_bfloat162 l = __floats2bfloat162_rn(a - hf.x, b - hf.y);
    hp = *(uint32_t*)&h;
    lp = *(uint32_t*)&l;
}

// gmem f32 [128][64] -> bf16 hi/lo smem, stride KSTR, optional scale
__device__ __forceinline__ void load_split(const float* __restrict__ g, char* smH, char* smL,
                                           float scale, int tid) {
    for (int idx = tid; idx < BM * 16; idx += NT) {
        int r = idx >> 4, c4 = (idx & 15) * 4;
        float4 v = *(const float4*)(g + (size_t)r * D_ + c4);
        v.x *= scale; v.y *= scale; v.z *= scale; v.w *= scale;
        uint32_t h0, l0, h1, l1;
        split2pack(v.x, v.y, h0, l0);
        split2pack(v.z, v.w, h1, l1);
        *(uint2*)(smH + r * RB + c4 * 2) = make_uint2(h0, h1);
        *(uint2*)(smL + r * RB + c4 * 2) = make_uint2(l0, l1);
    }
}

// scores for warp (wm,wn): c[mf][nf][4] over 32m x 64n, 3-split bf16 QK^T
__device__ __forceinline__ void qk_scores(uint32_t sb, int wm, int wn, int lid,
                                          float c[2][8][4]) {
    #pragma unroll
    for (int mf = 0; mf < 2; ++mf)
        #pragma unroll
        for (int nf = 0; nf < 8; ++nf)
            #pragma unroll
            for (int i = 0; i < 4; ++i) c[mf][nf][i] = 0.f;

    const int mi = lid >> 3, l7 = lid & 7;
    #pragma unroll
    for (int kc = 0; kc < 4; ++kc) {
        uint32_t aH[2][4], aL[2][4];
        const uint32_t acol = kc * 32 + (mi >> 1) * 16;
        #pragma unroll
        for (int mf = 0; mf < 2; ++mf) {
            uint32_t arow = (uint32_t)(32 * wm + 16 * mf + ((mi & 1) << 3) + l7) * RB;
            ldsm4(aH[mf], sb + OFF_QH + arow + acol);
            ldsm4(aL[mf], sb + OFF_QL + arow + acol);
        }
        const uint32_t bcol = kc * 32 + (mi & 1) * 16;
        #pragma unroll
        for (int nf2 = 0; nf2 < 4; ++nf2) {
            uint32_t bH[4], bL[4];
            uint32_t brow = (uint32_t)(64 * wn + nf2 * 16 + ((mi >> 1) << 3) + l7) * RB;
            ldsm4(bH, sb + OFF_KH + brow + bcol);
            ldsm4(bL, sb + OFF_KL + brow + bcol);
            #pragma unroll
            for (int mf = 0; mf < 2; ++mf) {
                mma_bf16(c[mf][2 * nf2],     aH[mf], bH[0], bH[1]);
                mma_bf16(c[mf][2 * nf2 + 1], aH[mf], bH[2], bH[3]);
                mma_bf16(c[mf][2 * nf2],     aH[mf], bL[0], bL[1]);
                mma_bf16(c[mf][2 * nf2 + 1], aH[mf], bL[2], bL[3]);
                mma_bf16(c[mf][2 * nf2],     aL[mf], bH[0], bH[1]);
                mma_bf16(c[mf][2 * nf2 + 1], aL[mf], bH[2], bH[3]);
            }
        }
    }
}

// ---------- pass A: row sums ----------
__global__ void __launch_bounds__(NT, 1)
sdpa_passA(const float* __restrict__ Q, const float* __restrict__ K,
           const int* __restrict__ mask)
{
    extern __shared__ char sm[];
    const uint32_t sb = smem_u32(sm);
    const int tid = threadIdx.x, wid = tid >> 5, lid = tid & 31;
    const int wm = wid & 3, wn = wid >> 2, g = lid >> 2, tl = lid & 3;
    const int bh = blockIdx.y, b = bh >> 4, q0 = blockIdx.x * BM;

    const float* Qg = Q + ((size_t)bh * S_ + q0) * D_;
    const float* Kg = K + (size_t)bh * S_ * D_;
    const int*   Mg = mask + (size_t)b * S_ * S_;

    load_split(Qg, sm + OFF_QH, sm + OFF_QL, 0.125f, tid);

    const int* mrow[4];
    #pragma unroll
    for (int i = 0; i < 4; ++i) {
        int row = q0 + 32 * wm + 16 * (i >> 1) + g + 8 * (i & 1);
        mrow[i] = Mg + (size_t)row * S_;
    }

    float rs[4] = {0.f, 0.f, 0.f, 0.f};

    for (int t = 0; t < NTILE; ++t) {
        if (t) __syncthreads();
        load_split(Kg + (size_t)t * BN * D_, sm + OFF_KH, sm + OFF_KL, 1.f, tid);
        __syncthreads();

        float c[2][8][4];
        qk_scores(sb, wm, wn, lid, c);

        const int k0 = t * BN;
        #pragma unroll
        for (int mf = 0; mf < 2; ++mf)
            #pragma unroll
            for (int nf = 0; nf < 8; ++nf) {
                int col = k0 + 64 * wn + 8 * nf + 2 * tl;
                int2 m0 = *(const int2*)(mrow[2 * mf] + col);
                int2 m1 = *(const int2*)(mrow[2 * mf + 1] + col);
                float e0 = m0.x ? __expf(c[mf][nf][0]) : 0.f;
                float e1 = m0.y ? __expf(c[mf][nf][1]) : 0.f;
                float e2 = m1.x ? __expf(c[mf][nf][2]) : 0.f;
                float e3 = m1.y ? __expf(c[mf][nf][3]) : 0.f;
                rs[2 * mf]     += e0 + e1;
                rs[2 * mf + 1] += e2 + e3;
            }
    }

    #pragma unroll
    for (int i = 0; i < 4; ++i) {
        rs[i] += __shfl_xor_sync(0xffffffffu, rs[i], 1);
        rs[i] += __shfl_xor_sync(0xffffffffu, rs[i], 2);
    }
    float* red = (float*)(sm + OFF_REDA);
    if (tl == 0) {
        #pragma unroll
        for (int i = 0; i < 4; ++i)
            red[wn * 128 + 32 * wm + 16 * (i >> 1) + g + 8 * (i & 1)] = rs[i];
    }
    __syncthreads();
    if (tid < 128)
        g_rsum[(size_t)bh * S_ + q0 + tid] = red[tid] + red[128 + tid];
}

// ---------- pass B: W + O ----------
__global__ void __launch_bounds__(NT, 1)
sdpa_passB(const float* __restrict__ Q, const float* __restrict__ K,
           const float* __restrict__ V, const int* __restrict__ mask,
           float* __restrict__ out, float* __restrict__ wts)
{
    extern __shared__ char sm[];
    const uint32_t sb = smem_u32(sm);
    const int tid = threadIdx.x, wid = tid >> 5, lid = tid & 31;
    const int wm = wid & 3, wn = wid >> 2, g = lid >> 2, tl = lid & 3;
    const int bh = blockIdx.y, b = bh >> 4, q0 = blockIdx.x * BM;

    const float* Qg = Q + ((size_t)bh * S_ + q0) * D_;
    const float* Kg = K + (size_t)bh * S_ * D_;
    const float* Vg = V + (size_t)bh * S_ * D_;
    const int*   Mg = mask + (size_t)b * S_ * S_;
    float*       Wg = wts + ((size_t)bh * S_ + q0) * S_;
    float*       Og = out + ((size_t)bh * S_ + q0) * D_;

    load_split(Qg, sm + OFF_QH, sm + OFF_QL, 0.125f, tid);
    float* rinv = (float*)(sm + OFF_RINV);
    if (tid < 128)
        rinv[tid] = 1.0f / g_rsum[(size_t)bh * S_ + q0 + tid];
    __syncthreads();

    const int* mrow[4];
    float*     wrow[4];
    float      ri[4];
    #pragma unroll
    for (int i = 0; i < 4; ++i) {
        int rl = 32 * wm + 16 * (i >> 1) + g + 8 * (i & 1);
        mrow[i] = Mg + (size_t)(q0 + rl) * S_;
        wrow[i] = Wg + (size_t)rl * S_;
        ri[i]   = rinv[rl];
    }

    float o[2][8][4];
    #pragma unroll
    for (int mf = 0; mf < 2; ++mf)
        #pragma unroll
        for (int df = 0; df < 8; ++df)
            #pragma unroll
            for (int i = 0; i < 4; ++i) o[mf][df][i] = 0.f;

    const int mi = lid >> 3, l7 = lid & 7;

    for (int t = 0; t < NTILE; ++t) {
        if (t) __syncthreads();
        load_split(Kg + (size_t)t * BN * D_, sm + OFF_KH, sm + OFF_KL, 1.f, tid);
        load_split(Vg + (size_t)t * BN * D_, sm + OFF_VH, sm + OFF_VL, 1.f, tid);
        __syncthreads();

        float c[2][8][4];
        qk_scores(sb, wm, wn, lid, c);

        const int k0 = t * BN;
        #pragma unroll
        for (int mf = 0; mf < 2; ++mf)
            #pragma unroll
            for (int nf = 0; nf < 8; ++nf) {
                int col = k0 + 64 * wn + 8 * nf + 2 * tl;
                int2 m0 = *(const int2*)(mrow[2 * mf] + col);
                int2 m1 = *(const int2*)(mrow[2 * mf + 1] + col);
                float e0 = m0.x ? __expf(c[mf][nf][0]) : 0.f;
                float e1 = m0.y ? __expf(c[mf][nf][1]) : 0.f;
                float e2 = m1.x ? __expf(c[mf][nf][2]) : 0.f;
                float e3 = m1.y ? __expf(c[mf][nf][3]) : 0.f;
                float2 w0 = make_float2(e0 * ri[2 * mf], e1 * ri[2 * mf]);
                float2 w1 = make_float2(e2 * ri[2 * mf + 1], e3 * ri[2 * mf + 1]);
                *(float2*)(wrow[2 * mf] + col)     = w0;
                *(float2*)(wrow[2 * mf + 1] + col) = w1;
                c[mf][nf][0] = e0; c[mf][nf][1] = e1;
                c[mf][nf][2] = e2; c[mf][nf][3] = e3;
            }

        // pack P (raw e) into PV A-fragments (bf16 hi/lo)
        uint32_t ph[2][4][4], pl[2][4][4];
        #pragma unroll
        for (int mf = 0; mf < 2; ++mf)
            #pragma unroll
            for (int kc = 0; kc < 4; ++kc) {
                split2pack(c[mf][2*kc][0],   c[mf][2*kc][1],   ph[mf][kc][0], pl[mf][kc][0]);
                split2pack(c[mf][2*kc][2],   c[mf][2*kc][3],   ph[mf][kc][1], pl[mf][kc][1]);
                split2pack(c[mf][2*kc+1][0], c[mf][2*kc+1][1], ph[mf][kc][2], pl[mf][kc][2]);
                split2pack(c[mf][2*kc+1][2], c[mf][2*kc+1][3], ph[mf][kc][3], pl[mf][kc][3]);
            }

        // PV: O += P * V  (3-split)
        #pragma unroll
        for (int kc = 0; kc < 4; ++kc) {
            uint32_t vrow = (uint32_t)(64 * wn + kc * 16 + ((mi & 1) << 3) + l7) * RB;
            #pragma unroll
            for (int db2 = 0; db2 < 4; ++db2) {
                uint32_t vh[4], vl[4];
                uint32_t addr = sb + OFF_VH + vrow + db2 * 32 + (mi >> 1) * 16;
                ldsm4t(vh, addr);
                ldsm4t(vl, addr + (OFF_VL - OFF_VH));
                #pragma unroll
                for (int mf = 0; mf < 2; ++mf) {
                    mma_bf16(o[mf][2 * db2],     ph[mf][kc], vh[0], vh[1]);
                    mma_bf16(o[mf][2 * db2 + 1], ph[mf][kc], vh[2], vh[3]);
                    mma_bf16(o[mf][2 * db2],     ph[mf][kc], vl[0], vl[1]);
                    mma_bf16(o[mf][2 * db2 + 1], ph[mf][kc], vl[2], vl[3]);
                    mma_bf16(o[mf][2 * db2],     pl[mf][kc], vh[0], vh[1]);
                    mma_bf16(o[mf][2 * db2 + 1], pl[mf][kc], vh[2], vh[3]);
                }
            }
        }
    }

    // epilogue: reduce the two wn halves, scale by rinv, store O
    __syncthreads();
    float* osm = (float*)(sm + OFF_KH);   // 32KB scratch (reuse K area)
    if (wn == 1) {
        #pragma unroll
        for (int mf = 0; mf < 2; ++mf)
            #pragma unroll
            for (int df = 0; df < 8; ++df) {
                int lr0 = wm * 32 + 16 * mf + g;
                int colc = 8 * df + 2 * tl;
                osm[lr0 * 64 + colc]           = o[mf][df][0];
                osm[lr0 * 64 + colc + 1]       = o[mf][df][1];
                osm[(lr0 + 8) * 64 + colc]     = o[mf][df][2];
                osm[(lr0 + 8) * 64 + colc + 1] = o[mf][df][3];
            }
    }
    __syncthreads();
    if (wn == 0) {
        #pragma unroll
        for (int mf = 0; mf < 2; ++mf)
            #pragma unroll
            for (int df = 0; df < 8; ++df) {
                int lr0 = wm * 32 + 16 * mf + g;
                int colc = 8 * df + 2 * tl;
                float2 w0 = make_float2(
                    (o[mf][df][0] + osm[lr0 * 64 + colc])     * ri[2 * mf],
                    (o[mf][df][1] + osm[lr0 * 64 + colc + 1]) * ri[2 * mf]);
                float2 w1 = make_float2(
                    (o[mf][df][2] + osm[(lr0 + 8) * 64 + colc])     * ri[2 * mf + 1],
                    (o[mf][df][3] + osm[(lr0 + 8) * 64 + colc + 1]) * ri[2 * mf + 1]);
                *(float2*)(Og + (size_t)lr0 * D_ + colc)       = w0;
                *(float2*)(Og + (size_t)(lr0 + 8) * D_ + colc) = w1;
            }
    }
}

extern "C" void kernel_launch(void* const* d_in, const int* in_sizes, int n_in,
                              void* d_out, int out_size)
{
    const float* Q    = (const float*)d_in[0];
    const float* K    = (const float*)d_in[1];
    const float* V    = (const float*)d_in[2];
    const int*   mask = (const int*)d_in[3];

    float* out = (float*)d_out;
    float* wts = out + (size_t)B_ * H_ * S_ * D_;

    cudaFuncSetAttribute(sdpa_passA, cudaFuncAttributeMaxDynamicSharedMemorySize, SMEM_A);
    cudaFuncSetAttribute(sdpa_passB, cudaFuncAttributeMaxDynamicSharedMemorySize, SMEM_B);

    dim3 grid(S_ / BM, B_ * H_);
    sdpa_passA<<<grid, NT, SMEM_A>>>(Q, K, mask);
    sdpa_passB<<<grid, NT, SMEM_B>>>(Q, K, V, mask, out, wts);
}

// round 5
// speedup vs baseline: 1.8467x; 1.3549x over previous
#include <cuda_runtime.h>
#include <cuda_bf16.h>
#include <cstdint>

// ScaledDotProductAttention B=4,H=16,S=2048,D=64 fp32 + mask [B,1,S,S] int32.
// out [B,H,S,D] then weights [B,H,S,S] concatenated in d_out.
//
// mma.sync (bf16 2-way split) flash-style, two-pass normalization.
// Round 4: occupancy restructure. Each warp owns 16 query rows fully;
// 128-key tiles processed in two 64-col chunks so score/P frags are 32 regs;
// Q fragments persist in registers; <=128 regs -> 2 CTAs/SM.

#define B_ 4
#define H_ 16
#define S_ 2048
#define D_ 64

constexpr int BM = 128, BN = 128, NT = 256, NTILE = S_ / BN;
constexpr int RB = 144;                    // bytes per bf16 smem row (72 elems)

// smem layout (passB):  K(hi/lo) reused for Q first, then V(hi/lo), rinv
constexpr int OFF_KH   = 0;
constexpr int OFF_KL   = OFF_KH + BM * RB;     // 18432
constexpr int OFF_VH   = OFF_KL + BM * RB;     // 36864
constexpr int OFF_VL   = OFF_VH + BM * RB;     // 55296
constexpr int OFF_RINV = OFF_VL + BM * RB;     // 73728
constexpr int SMEM_B   = OFF_RINV + 512;       // 74240
constexpr int SMEM_A   = OFF_KL + BM * RB;     // 36864 (Q then K only)

__device__ float g_rsum[B_ * H_ * S_];

// ---------- helpers ----------
__device__ __forceinline__ uint32_t smem_u32(const void* p) {
    uint32_t a;
    asm("{ .reg .u64 t; cvta.to.shared.u64 t, %1; cvt.u32.u64 %0, t; }" : "=r"(a) : "l"(p));
    return a;
}
__device__ __forceinline__ void ldsm4(uint32_t* r, uint32_t a) {
    asm volatile("ldmatrix.sync.aligned.m8n8.x4.shared.b16 {%0,%1,%2,%3}, [%4];"
                 : "=r"(r[0]), "=r"(r[1]), "=r"(r[2]), "=r"(r[3]) : "r"(a));
}
__device__ __forceinline__ void ldsm4t(uint32_t* r, uint32_t a) {
    asm volatile("ldmatrix.sync.aligned.m8n8.x4.trans.shared.b16 {%0,%1,%2,%3}, [%4];"
                 : "=r"(r[0]), "=r"(r[1]), "=r"(r[2]), "=r"(r[3]) : "r"(a));
}
__device__ __forceinline__ void mma_bf16(float* c, const uint32_t* a, uint32_t b0, uint32_t b1) {
    asm volatile(
        "mma.sync.aligned.m16n8k16.row.col.f32.bf16.bf16.f32 "
        "{%0,%1,%2,%3}, {%4,%5,%6,%7}, {%8,%9}, {%0,%1,%2,%3};"
        : "+f"(c[0]), "+f"(c[1]), "+f"(c[2]), "+f"(c[3])
        : "r"(a[0]), "r"(a[1]), "r"(a[2]), "r"(a[3]), "r"(b0), "r"(b1));
}
__device__ __forceinline__ void split2pack(float a, float b, uint32_t& hp, uint32_t& lp) {
    __nv_bfloat162 h = __floats2bfloat162_rn(a, b);
    float2 hf = __bfloat1622float2(h);
    __nv_bfloat162 l = __floats2bfloat162_rn(a - hf.x, b - hf.y);
    hp = *(uint32_t*)&h;
    lp = *(uint32_t*)&l;
}
__device__ __forceinline__ void load_split(const float* __restrict__ g, char* smH, char* smL,
                                           float scale, int tid) {
    for (int idx = tid; idx < BM * 16; idx += NT) {
        int r = idx >> 4, c4 = (idx & 15) * 4;
        float4 v = *(const float4*)(g + (size_t)r * D_ + c4);
        v.x *= scale; v.y *= scale; v.z *= scale; v.w *= scale;
        uint32_t h0, l0, h1, l1;
        split2pack(v.x, v.y, h0, l0);
        split2pack(v.z, v.w, h1, l1);
        *(uint2*)(smH + r * RB + c4 * 2) = make_uint2(h0, h1);
        *(uint2*)(smL + r * RB + c4 * 2) = make_uint2(l0, l1);
    }
}

// scores for one 16m x 64n chunk (3-split bf16), Q frags in regs
__device__ __forceinline__ void qk_chunk(uint32_t sb, int co, int mi, int l7,
                                         const uint32_t aQH[4][4], const uint32_t aQL[4][4],
                                         float c[8][4]) {
    #pragma unroll
    for (int nf = 0; nf < 8; ++nf)
        #pragma unroll
        for (int i = 0; i < 4; ++i) c[nf][i] = 0.f;

    #pragma unroll
    for (int kc = 0; kc < 4; ++kc) {
        const uint32_t bcol = kc * 32 + (mi & 1) * 16;
        #pragma unroll
        for (int nf2 = 0; nf2 < 4; ++nf2) {
            uint32_t bH[4], bL[4];
            uint32_t brow = (uint32_t)(co + nf2 * 16 + ((mi >> 1) << 3) + l7) * RB;
            ldsm4(bH, sb + OFF_KH + brow + bcol);
            ldsm4(bL, sb + OFF_KL + brow + bcol);
            mma_bf16(c[2 * nf2],     aQH[kc], bH[0], bH[1]);
            mma_bf16(c[2 * nf2 + 1], aQH[kc], bH[2], bH[3]);
            mma_bf16(c[2 * nf2],     aQH[kc], bL[0], bL[1]);
            mma_bf16(c[2 * nf2 + 1], aQH[kc], bL[2], bL[3]);
            mma_bf16(c[2 * nf2],     aQL[kc], bH[0], bH[1]);
            mma_bf16(c[2 * nf2 + 1], aQL[kc], bH[2], bH[3]);
        }
    }
}

// ---------- pass A: row sums ----------
__global__ void __launch_bounds__(NT, 2)
sdpa_passA(const float* __restrict__ Q, const float* __restrict__ K,
           const int* __restrict__ mask)
{
    extern __shared__ char sm[];
    const uint32_t sb = smem_u32(sm);
    const int tid = threadIdx.x, w = tid >> 5, lid = tid & 31;
    const int g = lid >> 2, tl = lid & 3, mi = lid >> 3, l7 = lid & 7;
    const int bh = blockIdx.y, b = bh >> 4, q0 = blockIdx.x * BM;

    const float* Qg = Q + ((size_t)bh * S_ + q0) * D_;
    const float* Kg = K + (size_t)bh * S_ * D_;
    const int*   Mg = mask + (size_t)b * S_ * S_;

    load_split(Qg, sm + OFF_KH, sm + OFF_KL, 0.125f, tid);
    __syncthreads();

    uint32_t aQH[4][4], aQL[4][4];
    {
        uint32_t arow = (uint32_t)(16 * w + ((mi & 1) << 3) + l7) * RB;
        #pragma unroll
        for (int kc = 0; kc < 4; ++kc) {
            uint32_t acol = kc * 32 + (mi >> 1) * 16;
            ldsm4(aQH[kc], sb + OFF_KH + arow + acol);
            ldsm4(aQL[kc], sb + OFF_KL + arow + acol);
        }
    }

    const int r0 = 16 * w + g;
    const int* m0p = Mg + (size_t)(q0 + r0) * S_;
    const int* m1p = Mg + (size_t)(q0 + r0 + 8) * S_;
    float rs0 = 0.f, rs1 = 0.f;

    for (int t = 0; t < NTILE; ++t) {
        __syncthreads();
        load_split(Kg + (size_t)t * BN * D_, sm + OFF_KH, sm + OFF_KL, 1.f, tid);
        __syncthreads();

        #pragma unroll
        for (int ch2 = 0; ch2 < 2; ++ch2) {
            const int co = 64 * ch2;
            float c[8][4];
            qk_chunk(sb, co, mi, l7, aQH, aQL, c);
            const int colb = t * BN + co;
            #pragma unroll
            for (int nf = 0; nf < 8; ++nf) {
                int col = colb + 8 * nf + 2 * tl;
                int2 mA = *(const int2*)(m0p + col);
                int2 mB = *(const int2*)(m1p + col);
                rs0 += (mA.x ? __expf(c[nf][0]) : 0.f) + (mA.y ? __expf(c[nf][1]) : 0.f);
                rs1 += (mB.x ? __expf(c[nf][2]) : 0.f) + (mB.y ? __expf(c[nf][3]) : 0.f);
            }
        }
    }

    rs0 += __shfl_xor_sync(0xffffffffu, rs0, 1);
    rs0 += __shfl_xor_sync(0xffffffffu, rs0, 2);
    rs1 += __shfl_xor_sync(0xffffffffu, rs1, 1);
    rs1 += __shfl_xor_sync(0xffffffffu, rs1, 2);
    if (tl == 0) {
        g_rsum[(size_t)bh * S_ + q0 + r0]     = rs0;
        g_rsum[(size_t)bh * S_ + q0 + r0 + 8] = rs1;
    }
}

// ---------- pass B: W + O ----------
__global__ void __launch_bounds__(NT, 2)
sdpa_passB(const float* __restrict__ Q, const float* __restrict__ K,
           const float* __restrict__ V, const int* __restrict__ mask,
           float* __restrict__ out, float* __restrict__ wts)
{
    extern __shared__ char sm[];
    const uint32_t sb = smem_u32(sm);
    const int tid = threadIdx.x, w = tid >> 5, lid = tid & 31;
    const int g = lid >> 2, tl = lid & 3, mi = lid >> 3, l7 = lid & 7;
    const int bh = blockIdx.y, b = bh >> 4, q0 = blockIdx.x * BM;

    const float* Qg = Q + ((size_t)bh * S_ + q0) * D_;
    const float* Kg = K + (size_t)bh * S_ * D_;
    const float* Vg = V + (size_t)bh * S_ * D_;
    const int*   Mg = mask + (size_t)b * S_ * S_;
    float*       Wg = wts + ((size_t)bh * S_ + q0) * S_;
    float*       Og = out + ((size_t)bh * S_ + q0) * D_;

    load_split(Qg, sm + OFF_KH, sm + OFF_KL, 0.125f, tid);
    float* rinv = (float*)(sm + OFF_RINV);
    if (tid < 128)
        rinv[tid] = 1.0f / g_rsum[(size_t)bh * S_ + q0 + tid];
    __syncthreads();

    uint32_t aQH[4][4], aQL[4][4];
    {
        uint32_t arow = (uint32_t)(16 * w + ((mi & 1) << 3) + l7) * RB;
        #pragma unroll
        for (int kc = 0; kc < 4; ++kc) {
            uint32_t acol = kc * 32 + (mi >> 1) * 16;
            ldsm4(aQH[kc], sb + OFF_KH + arow + acol);
            ldsm4(aQL[kc], sb + OFF_KL + arow + acol);
        }
    }

    const int r0 = 16 * w + g;
    const float ri0 = rinv[r0], ri1 = rinv[r0 + 8];
    const int* m0p = Mg + (size_t)(q0 + r0) * S_;
    const int* m1p = Mg + (size_t)(q0 + r0 + 8) * S_;
    float* w0p = Wg + (size_t)r0 * S_;
    float* w1p = Wg + (size_t)(r0 + 8) * S_;

    float o[8][4];
    #pragma unroll
    for (int df = 0; df < 8; ++df)
        #pragma unroll
        for (int i = 0; i < 4; ++i) o[df][i] = 0.f;

    for (int t = 0; t < NTILE; ++t) {
        __syncthreads();
        load_split(Kg + (size_t)t * BN * D_, sm + OFF_KH, sm + OFF_KL, 1.f, tid);
        load_split(Vg + (size_t)t * BN * D_, sm + OFF_VH, sm + OFF_VL, 1.f, tid);
        __syncthreads();

        #pragma unroll
        for (int ch2 = 0; ch2 < 2; ++ch2) {
            const int co = 64 * ch2;
            float c[8][4];
            qk_chunk(sb, co, mi, l7, aQH, aQL, c);

            // exp + mask + normalized W write; c <- raw e
            const int colb = t * BN + co;
            #pragma unroll
            for (int nf = 0; nf < 8; ++nf) {
                int col = colb + 8 * nf + 2 * tl;
                int2 mA = *(const int2*)(m0p + col);
                int2 mB = *(const int2*)(m1p + col);
                float e0 = mA.x ? __expf(c[nf][0]) : 0.f;
                float e1 = mA.y ? __expf(c[nf][1]) : 0.f;
                float e2 = mB.x ? __expf(c[nf][2]) : 0.f;
                float e3 = mB.y ? __expf(c[nf][3]) : 0.f;
                *(float2*)(w0p + col) = make_float2(e0 * ri0, e1 * ri0);
                *(float2*)(w1p + col) = make_float2(e2 * ri1, e3 * ri1);
                c[nf][0] = e0; c[nf][1] = e1; c[nf][2] = e2; c[nf][3] = e3;
            }

            // pack P chunk into PV A-frags
            uint32_t ph[4][4], pl[4][4];
            #pragma unroll
            for (int kc = 0; kc < 4; ++kc) {
                split2pack(c[2*kc][0],   c[2*kc][1],   ph[kc][0], pl[kc][0]);
                split2pack(c[2*kc][2],   c[2*kc][3],   ph[kc][1], pl[kc][1]);
                split2pack(c[2*kc+1][0], c[2*kc+1][1], ph[kc][2], pl[kc][2]);
                split2pack(c[2*kc+1][2], c[2*kc+1][3], ph[kc][3], pl[kc][3]);
            }

            // PV for this 64-key chunk: O += P * V (3-split)
            #pragma unroll
            for (int kc = 0; kc < 4; ++kc) {
                uint32_t vrow = (uint32_t)(co + kc * 16 + ((mi & 1) << 3) + l7) * RB;
                #pragma unroll
                for (int db2 = 0; db2 < 4; ++db2) {
                    uint32_t vh[4], vl[4];
                    uint32_t va = sb + OFF_VH + vrow + db2 * 32 + (mi >> 1) * 16;
                    ldsm4t(vh, va);
                    ldsm4t(vl, va + (OFF_VL - OFF_VH));
                    mma_bf16(o[2 * db2],     ph[kc], vh[0], vh[1]);
                    mma_bf16(o[2 * db2 + 1], ph[kc], vh[2], vh[3]);
                    mma_bf16(o[2 * db2],     ph[kc], vl[0], vl[1]);
                    mma_bf16(o[2 * db2 + 1], ph[kc], vl[2], vl[3]);
                    mma_bf16(o[2 * db2],     pl[kc], vh[0], vh[1]);
                    mma_bf16(o[2 * db2 + 1], pl[kc], vh[2], vh[3]);
                }
            }
        }
    }

    // epilogue: scale by rinv, store O (each warp owns its rows)
    #pragma unroll
    for (int df = 0; df < 8; ++df) {
        int colc = 8 * df + 2 * tl;
        *(float2*)(Og + (size_t)r0 * D_ + colc) =
            make_float2(o[df][0] * ri0, o[df][1] * ri0);
        *(float2*)(Og + (size_t)(r0 + 8) * D_ + colc) =
            make_float2(o[df][2] * ri1, o[df][3] * ri1);
    }
}

extern "C" void kernel_launch(void* const* d_in, const int* in_sizes, int n_in,
                              void* d_out, int out_size)
{
    const float* Q    = (const float*)d_in[0];
    const float* K    = (const float*)d_in[1];
    const float* V    = (const float*)d_in[2];
    const int*   mask = (const int*)d_in[3];

    float* out = (float*)d_out;
    float* wts = out + (size_t)B_ * H_ * S_ * D_;

    cudaFuncSetAttribute(sdpa_passA, cudaFuncAttributeMaxDynamicSharedMemorySize, SMEM_A);
    cudaFuncSetAttribute(sdpa_passB, cudaFuncAttributeMaxDynamicSharedMemorySize, SMEM_B);

    dim3 grid(S_ / BM, B_ * H_);
    sdpa_passA<<<grid, NT, SMEM_A>>>(Q, K, mask);
    sdpa_passB<<<grid, NT, SMEM_B>>>(Q, K, V, mask, out, wts);
}